// round 1
// baseline (speedup 1.0000x reference)
#include <cuda_runtime.h>
#include <cstdint>

// ---------------------------------------------------------------------------
// SpecAugment on GB300.
// Reproduces jax.random (threefry2x32, partitionable path, default in
// modern JAX) bit-exactly to derive the frequency / time masks, then does a
// pure streaming multiply-by-{0,1}.  B=128, T=4000, F=128.
// ---------------------------------------------------------------------------

#define N_FREQ_MASKS   2
#define FREQ_MASK_SIZE 27.0f
#define TIME_MASK_PCT  0.25f

// Scratch: frequency-mask multiplier per f (0.0 or 1.0), and per-batch
// time-mask intervals [ts0,te0), [ts1,te1).
__device__ float g_fmul[128];
__device__ int4  g_trange[128];

// ---- Threefry2x32 (20 rounds), identical to jax._src.prng.threefry2x32 ----
__device__ __forceinline__ uint2 threefry2x32(unsigned k0, unsigned k1,
                                              unsigned x0, unsigned x1) {
    unsigned ks2 = k0 ^ k1 ^ 0x1BD11BDAu;
    x0 += k0; x1 += k1;
#define TF_RND(r) { x0 += x1; x1 = __funnelshift_l(x1, x1, (r)); x1 ^= x0; }
    TF_RND(13) TF_RND(15) TF_RND(26) TF_RND(6)
    x0 += k1;  x1 += ks2 + 1u;
    TF_RND(17) TF_RND(29) TF_RND(16) TF_RND(24)
    x0 += ks2; x1 += k0 + 2u;
    TF_RND(13) TF_RND(15) TF_RND(26) TF_RND(6)
    x0 += k0;  x1 += k1 + 3u;
    TF_RND(17) TF_RND(29) TF_RND(16) TF_RND(24)
    x0 += k1;  x1 += ks2 + 4u;
    TF_RND(13) TF_RND(15) TF_RND(26) TF_RND(6)
    x0 += ks2; x1 += k0 + 5u;
#undef TF_RND
    return make_uint2(x0, x1);
}

// Partitionable 32-bit random bits for flat element index j under subkey k:
// bits = r0 ^ r1 of threefry2x32(k, (hi32(j)=0, lo32(j)=j))
__device__ __forceinline__ unsigned rbits32(uint2 k, unsigned j) {
    uint2 h = threefry2x32(k.x, k.y, 0u, j);
    return h.x ^ h.y;
}

// jax.random.uniform mantissa trick: [1,2) bitcast minus 1.
__device__ __forceinline__ float bits_to_unit(unsigned bits) {
    return __uint_as_float((bits >> 9) | 0x3F800000u) - 1.0f;
}

// ---------------------------------------------------------------------------
// Setup: one block of 128 threads. Thread i doubles as frequency bin i and
// batch index i (B == F == 128 here).
// ---------------------------------------------------------------------------
__global__ void specaug_setup_kernel(const int* __restrict__ x_len,
                                     int B, int F) {
    const int i = threadIdx.x;

    // split(key(42), 3) fold-like: child i = threefry(key, (0, i))
    const uint2 kf = threefry2x32(0u, 42u, 0u, 0u);
    const uint2 kv = threefry2x32(0u, 42u, 0u, 1u);
    const uint2 ks = threefry2x32(0u, 42u, 0u, 2u);

    // ---- frequency masks (shared across batch): uf shape (2,2), flat j ----
    float u00 = bits_to_unit(rbits32(kf, 0u));  // uf[0,0]
    float u01 = bits_to_unit(rbits32(kf, 1u));  // uf[0,1]
    float u10 = bits_to_unit(rbits32(kf, 2u));  // uf[1,0]
    float u11 = bits_to_unit(rbits32(kf, 3u));  // uf[1,1]

    float Ff = (float)F;
    float fv0 = __fmul_rn(u00, FREQ_MASK_SIZE);
    float fb0 = __fmul_rn(u01, __fsub_rn(Ff, fv0));
    float fs0 = floorf(fb0);
    float fe0 = floorf(__fadd_rn(fb0, fv0));
    float fv1 = __fmul_rn(u10, FREQ_MASK_SIZE);
    float fb1 = __fmul_rn(u11, __fsub_rn(Ff, fv1));
    float fs1 = floorf(fb1);
    float fe1 = floorf(__fadd_rn(fb1, fv1));

    if (i < F) {
        float ff = (float)i;
        bool fm = (ff >= fs0 && ff < fe0) || (ff >= fs1 && ff < fe1);
        g_fmul[i] = fm ? 0.0f : 1.0f;
    }

    // ---- time masks for batch i: uv/us shape (B,2), flat j = 2*i + m ----
    if (i < B) {
        float xl = (float)x_len[i];
        float tparam = floorf(__fmul_rn(TIME_MASK_PCT, xl));

        float uv0 = bits_to_unit(rbits32(kv, 2u * i));
        float uv1 = bits_to_unit(rbits32(kv, 2u * i + 1u));
        float us0 = bits_to_unit(rbits32(ks, 2u * i));
        float us1 = bits_to_unit(rbits32(ks, 2u * i + 1u));

        float tv0 = __fmul_rn(uv0, tparam);
        float tb0 = __fmul_rn(us0, __fsub_rn(xl, tv0));
        int   ts0 = (int)floorf(tb0);
        int   te0 = (int)floorf(__fadd_rn(tb0, tv0));

        float tv1 = __fmul_rn(uv1, tparam);
        float tb1 = __fmul_rn(us1, __fsub_rn(xl, tv1));
        int   ts1 = (int)floorf(tb1);
        int   te1 = (int)floorf(__fadd_rn(tb1, tv1));

        g_trange[i] = make_int4(ts0, te0, ts1, te1);
    }
}

// ---------------------------------------------------------------------------
// Streaming apply: out = x * fmul[f] * (tmask ? 0 : 1).
// Block = 256 threads = 8 time-rows x 32 float4 lanes. Grid = (T/8, B).
// ---------------------------------------------------------------------------
__global__ void __launch_bounds__(256)
specaug_apply_kernel(const float4* __restrict__ x,
                     float4* __restrict__ out,
                     int T) {
    const int b = blockIdx.y;
    const int t = blockIdx.x * 8 + (threadIdx.x >> 5);
    const int q = threadIdx.x & 31;      // float4 lane within the F=128 row
    if (t >= T) return;

    const size_t idx = ((size_t)b * T + t) * 32 + q;
    float4 v = x[idx];

    int4 tr = g_trange[b];
    bool tmask = (t >= tr.x && t < tr.y) || (t >= tr.z && t < tr.w);

    float4 fm = reinterpret_cast<const float4*>(g_fmul)[q];

    float4 r;
    if (tmask) {
        r = make_float4(0.f, 0.f, 0.f, 0.f);
    } else {
        r.x = v.x * fm.x;
        r.y = v.y * fm.y;
        r.z = v.z * fm.z;
        r.w = v.w * fm.w;
    }
    out[idx] = r;
}

extern "C" void kernel_launch(void* const* d_in, const int* in_sizes, int n_in,
                              void* d_out, int out_size) {
    const float* x     = (const float*)d_in[0];
    const int*   x_len = (const int*)d_in[1];
    float*       out   = (float*)d_out;

    const int B = in_sizes[1];                 // 128
    const int F = 128;                         // fixed by problem
    const int T = in_sizes[0] / (B * F);       // 4000

    specaug_setup_kernel<<<1, 128>>>(x_len, B, F);

    dim3 grid((T + 7) / 8, B);
    specaug_apply_kernel<<<grid, 256>>>(
        (const float4*)x, (float4*)out, T);
    (void)n_in; (void)out_size;
}